// round 3
// baseline (speedup 1.0000x reference)
#include <cuda_runtime.h>
#include <math.h>

#define Bz 32
#define SL 512
#define VD 768
#define HD 512
#define NBLK 128   // persistent blocks for recurrence (64 fwd + 64 bwd)

// ---------------- scratch (device globals; no allocation allowed) ----------------
__device__ __align__(16) float g_xgf[(size_t)SL * 2048 * Bz];   // [t][g][b]  134 MB
__device__ __align__(16) float g_xgb[(size_t)SL * 2048 * Bz];   // [t][g][b]  134 MB
__device__ __align__(16) float g_skip[(size_t)SL * 1024 * Bz];  // [t][g][b]   67 MB
__device__ __align__(16) float g_hsf[(size_t)SL * HD * Bz];     // [t][j][b]   33 MB
__device__ __align__(16) float g_hsb[(size_t)SL * HD * Bz];     // [t][j][b]   33 MB
__device__ __align__(16) float g_h[4 * HD * Bz];                // [dir*2+phase][j][b]
__device__ unsigned gbar_cnt = 0;
__device__ unsigned gbar_gen = 0;

// ---------------- fp32 tiled GEMM: out[t][n][b] = values[b][t][:] @ W[:, n] + bias[n] ----
// A: values [32][512][768] (row m = t*32+b), B: W [768][N] row-major.
__global__ __launch_bounds__(256, 2) void gemm_xproj(
    const float* __restrict__ A,
    const float* __restrict__ W,
    const float* __restrict__ bias,
    int N, int which)
{
    float* out = (which == 0) ? g_xgf : ((which == 1) ? g_xgb : g_skip);

    __shared__ float As[16][128];  // [k][m]
    __shared__ float Bs[16][128];  // [k][n]

    const int bm = blockIdx.y, bn = blockIdx.x;
    const int tid = threadIdx.x;
    const int tx = tid & 15, ty = tid >> 4;

    float acc[8][8];
#pragma unroll
    for (int i = 0; i < 8; i++)
#pragma unroll
        for (int j = 0; j < 8; j++) acc[i][j] = 0.f;

    for (int k0 = 0; k0 < VD; k0 += 16) {
#pragma unroll
        for (int l = 0; l < 2; l++) {
            int q = tid + l * 256;           // 0..511
            // A tile: 128 rows x 16 k  (4 float4 per row)
            int row = q >> 2;
            int kq = (q & 3) * 4;
            int m = bm * 128 + row;
            int bb = m & 31, tt = m >> 5;
            float4 av = *(const float4*)(A + ((size_t)bb * SL + tt) * VD + k0 + kq);
            As[kq + 0][row] = av.x; As[kq + 1][row] = av.y;
            As[kq + 2][row] = av.z; As[kq + 3][row] = av.w;
            // B tile: 16 k x 128 n
            int kr = q >> 5;
            int nq = (q & 31) * 4;
            float4 bv = *(const float4*)(W + (size_t)(k0 + kr) * N + bn * 128 + nq);
            *(float4*)&Bs[kr][nq] = bv;
        }
        __syncthreads();

#pragma unroll
        for (int kk = 0; kk < 16; kk++) {
            float ra[8], rb[8];
            *(float4*)&ra[0] = *(const float4*)&As[kk][ty * 8];
            *(float4*)&ra[4] = *(const float4*)&As[kk][ty * 8 + 4];
            *(float4*)&rb[0] = *(const float4*)&Bs[kk][tx * 8];
            *(float4*)&rb[4] = *(const float4*)&Bs[kk][tx * 8 + 4];
#pragma unroll
            for (int i = 0; i < 8; i++)
#pragma unroll
                for (int j = 0; j < 8; j++) acc[i][j] = fmaf(ra[i], rb[j], acc[i][j]);
        }
        __syncthreads();
    }

#pragma unroll
    for (int i = 0; i < 8; i++) {
        int m = bm * 128 + ty * 8 + i;
        int bb = m & 31, tt = m >> 5;
#pragma unroll
        for (int j = 0; j < 8; j++) {
            int n = bn * 128 + tx * 8 + j;
            out[(size_t)tt * N * Bz + (size_t)n * Bz + bb] = acc[i][j] + bias[n];
        }
    }
}

// ---------------- persistent bidirectional LSTM recurrence ----------------
__device__ __forceinline__ float sigm(float x) { return 1.f / (1.f + expf(-x)); }

__device__ __forceinline__ unsigned ld_acq(const unsigned* p) {
    unsigned v;
    asm volatile("ld.acquire.gpu.u32 %0, [%1];" : "=r"(v) : "l"(p) : "memory");
    return v;
}
__device__ __forceinline__ void st_rel(unsigned* p, unsigned v) {
    asm volatile("st.release.gpu.u32 [%0], %1;" :: "l"(p), "r"(v) : "memory");
}

// Grid-wide barrier: counter + generation, release/acquire semantics.
__device__ __forceinline__ void grid_bar() {
    __syncthreads();
    if (threadIdx.x == 0) {
        __threadfence();
        unsigned g = ld_acq(&gbar_gen);
        unsigned old = atomicAdd(&gbar_cnt, 1u);
        if (old == NBLK - 1) {
            gbar_cnt = 0;
            st_rel(&gbar_gen, g + 1);
        } else {
            int backoff = 32;
            while (ld_acq(&gbar_gen) == g) {
                __nanosleep(backoff);
                if (backoff < 1024) backoff <<= 1;
            }
        }
    }
    __syncthreads();
}

__global__ __launch_bounds__(256, 1) void lstm_recur(
    const float* __restrict__ Whf,
    const float* __restrict__ Whb,
    const float* __restrict__ alphas)
{
    extern __shared__ float smem[];
    float4* w4 = (float4*)smem;          // [c(8)][k(512)]  64 KB
    float* sh_h = smem + 16384;          // [k(512)][b(32)] 64 KB

    const int bid = blockIdx.x;
    const int dir = (bid >= NBLK / 2) ? 1 : 0;
    const int blk = dir ? bid - NBLK / 2 : bid;
    const float* Wh = dir ? Whb : Whf;
    const float* xg = dir ? g_xgb : g_xgf;
    float* hs = dir ? g_hsb : g_hsf;

    const int tid = threadIdx.x;
    const int c = tid >> 5;          // local h-column 0..7
    const int lane = tid & 31;       // batch
    const int j = blk * 8 + c;       // global h-column

    // Stage Wh slice into smem once: w4[c][k] = (W[k][j], W[k][512+j], W[k][1024+j], W[k][1536+j])
    for (int k = lane; k < HD; k += 32) {
        const float* wr = Wh + (size_t)k * 2048 + j;
        w4[c * 512 + k] = make_float4(wr[0], wr[512], wr[1024], wr[1536]);
    }
    __syncthreads();

    float cst = 0.f, hprev = 0.f;
    const float4* wp = w4 + c * 512;

    for (int s = 0; s < SL; s++) {
        const int t = dir ? (SL - 1 - s) : s;

        if (s > 0) {  // stage h(s-1) from global double-buffer (bypass L1)
            const float4* src = (const float4*)(g_h + (size_t)(dir * 2 + ((s + 1) & 1)) * (HD * Bz));
            float4* dst = (float4*)sh_h;
#pragma unroll 4
            for (int i = tid; i < (HD * Bz) / 4; i += 256) dst[i] = __ldcg(src + i);
        }
        __syncthreads();

        float ai = 0.f, af = 0.f, ag = 0.f, ao = 0.f;
        if (s > 0) {
            const float* hp = sh_h + lane;
#pragma unroll 8
            for (int k = 0; k < HD; k++) {
                float4 w = wp[k];
                float hv = hp[k * 32];
                ai = fmaf(w.x, hv, ai);
                af = fmaf(w.y, hv, af);
                ag = fmaf(w.z, hv, ag);
                ao = fmaf(w.w, hv, ao);
            }
        }

        const size_t base = (size_t)t * (2048 * Bz) + lane;
        float xi = xg[base + (size_t)(0 * HD + j) * Bz];
        float xf = xg[base + (size_t)(1 * HD + j) * Bz];
        float xv = xg[base + (size_t)(2 * HD + j) * Bz];
        float xo = xg[base + (size_t)(3 * HD + j) * Bz];

        float gi = sigm(ai + xi);
        float gf = sigm(af + xf);
        float gg = tanhf(ag + xv);
        float go = sigm(ao + xo);

        float cn = gf * cst + gi * gg;
        float hn = go * tanhf(cn);

        float a = alphas[lane * SL + t];
        cst = a * cn + (1.f - a) * cst;
        float h2 = a * hn + (1.f - a) * hprev;
        hprev = h2;

        hs[(size_t)t * (HD * Bz) + j * 32 + lane] = h2;
        g_h[(size_t)(dir * 2 + (s & 1)) * (HD * Bz) + j * 32 + lane] = h2;

        grid_bar();
    }
}

// ---------------- pooling ----------------
__global__ void pool_kernel(const float* __restrict__ alphas, float* __restrict__ out)
{
    const int tid = blockIdx.x * blockDim.x + threadIdx.x;  // 32768 threads
    const int b = tid & 31;
    const int g = tid >> 5;  // 0..1023
    if (g >= 1024) return;

    const float* top = (g < HD) ? (g_hsf + (size_t)g * 32 + b)
                                : (g_hsb + (size_t)(g - HD) * 32 + b);
    const float* sk = g_skip + (size_t)g * 32 + b;

    float sum = 0.f, asum = 0.f, mx = -INFINITY;
    for (int t = 0; t < SL; t++) {
        float a = alphas[b * SL + t];
        float r = (top[(size_t)t * (HD * Bz)] + sk[(size_t)t * (1024 * Bz)]) * a;
        sum += r;
        asum += a;
        if (a > 0.f) mx = fmaxf(mx, r);
    }
    float mean = sum / (asum + 1e-6f);
    if (isinf(mx)) mx = 0.f;
    out[b * 2048 + g] = mean;
    out[b * 2048 + 1024 + g] = mx;
}

// ---------------- launch ----------------
extern "C" void kernel_launch(void* const* d_in, const int* in_sizes, int n_in,
                              void* d_out, int out_size)
{
    const float* values = (const float*)d_in[0];
    const float* alphas = (const float*)d_in[1];
    const float* Wx_f = (const float*)d_in[2];
    const float* Wh_f = (const float*)d_in[3];
    const float* b_f  = (const float*)d_in[4];
    const float* Wx_b = (const float*)d_in[5];
    const float* Wh_b = (const float*)d_in[6];
    const float* b_b  = (const float*)d_in[7];
    const float* Ws   = (const float*)d_in[8];
    const float* bs   = (const float*)d_in[9];
    float* out = (float*)d_out;

    cudaFuncSetAttribute(lstm_recur, cudaFuncAttributeMaxDynamicSharedMemorySize, 131072);

    dim3 blk(256);
    gemm_xproj<<<dim3(2048 / 128, (Bz * SL) / 128), blk>>>(values, Wx_f, b_f, 2048, 0);
    gemm_xproj<<<dim3(2048 / 128, (Bz * SL) / 128), blk>>>(values, Wx_b, b_b, 2048, 1);
    gemm_xproj<<<dim3(1024 / 128, (Bz * SL) / 128), blk>>>(values, Ws, bs, 1024, 2);
    lstm_recur<<<NBLK, 256, 131072>>>(Wh_f, Wh_b, alphas);
    pool_kernel<<<(Bz * 1024) / 256, 256>>>(alphas, out);
}

// round 4
// speedup vs baseline: 1.7234x; 1.7234x over previous
#include <cuda_runtime.h>
#include <math.h>
#include <stdint.h>

#define Bz 32
#define SL 512
#define VD 768
#define HD 512
#define NT 5120     // fused N: 2048 (Wx_f) + 2048 (Wx_b) + 1024 (Ws)
#define NBLK 128    // persistent blocks for recurrence (64 fwd + 64 bwd)

// ---------------- scratch (device globals; no allocation allowed) ----------------
__device__ __align__(16) float g_xgf[(size_t)SL * 2048 * Bz];   // [t][g][b]
__device__ __align__(16) float g_xgb[(size_t)SL * 2048 * Bz];   // [t][g][b]
__device__ __align__(16) float g_skip[(size_t)SL * 1024 * Bz];  // [t][g][b]
__device__ __align__(16) float g_hsf[(size_t)SL * HD * Bz];     // [t][j][b]
__device__ __align__(16) float g_hsb[(size_t)SL * HD * Bz];     // [t][j][b]
__device__ __align__(16) float g_h[4 * HD * Bz];                // [dir*2+phase][j][b]
__device__ unsigned gbar_cnt = 0;
__device__ unsigned gbar_gen = 0;

// tf32-split operands
__device__ __align__(16) float g_Ahi[(size_t)(Bz * SL) * VD];   // [m=t*32+b][v]
__device__ __align__(16) float g_Alo[(size_t)(Bz * SL) * VD];
__device__ __align__(16) float g_Whi[(size_t)VD * NT];          // [v][n]  (concat)
__device__ __align__(16) float g_Wlo[(size_t)VD * NT];
__device__ __align__(16) float g_biasc[NT];

// ---------------- helpers ----------------
__device__ __forceinline__ float to_tf32(float x) {
    float r;
    asm("cvt.rna.tf32.f32 %0, %1;" : "=f"(r) : "f"(x));
    return r;
}

__device__ __forceinline__ void mma8(float* d, const uint32_t* a, const uint32_t* b) {
    asm volatile(
        "mma.sync.aligned.m16n8k8.row.col.f32.tf32.tf32.f32 "
        "{%0,%1,%2,%3}, {%4,%5,%6,%7}, {%8,%9}, {%0,%1,%2,%3};"
        : "+f"(d[0]), "+f"(d[1]), "+f"(d[2]), "+f"(d[3])
        : "r"(a[0]), "r"(a[1]), "r"(a[2]), "r"(a[3]), "r"(b[0]), "r"(b[1]));
}

// ---------------- split kernels ----------------
__global__ void split_A(const float* __restrict__ values) {
    const int m = blockIdx.x;              // 0..16383, m = t*32 + b
    const int b = m & 31, t = m >> 5;
    const float* src = values + ((size_t)b * SL + t) * VD;
    for (int v = threadIdx.x; v < VD; v += 256) {
        float x = src[v];
        float hi = to_tf32(x);
        float lo = to_tf32(x - hi);
        g_Ahi[(size_t)m * VD + v] = hi;
        g_Alo[(size_t)m * VD + v] = lo;
    }
}

__global__ void split_W(const float* __restrict__ Wxf, const float* __restrict__ Wxb,
                        const float* __restrict__ Ws,
                        const float* __restrict__ bf, const float* __restrict__ bb_,
                        const float* __restrict__ bs) {
    const int r = blockIdx.x;  // 0..767
    for (int c = threadIdx.x; c < NT; c += 256) {
        float x = (c < 2048) ? Wxf[(size_t)r * 2048 + c]
                : (c < 4096) ? Wxb[(size_t)r * 2048 + (c - 2048)]
                             : Ws[(size_t)r * 1024 + (c - 4096)];
        float hi = to_tf32(x);
        float lo = to_tf32(x - hi);
        g_Whi[(size_t)r * NT + c] = hi;
        g_Wlo[(size_t)r * NT + c] = lo;
    }
    if (r == 0) {
        for (int c = threadIdx.x; c < NT; c += 256)
            g_biasc[c] = (c < 2048) ? bf[c] : (c < 4096) ? bb_[c - 2048] : bs[c - 4096];
    }
}

// ---------------- fused tf32 3x GEMM: C[m][n] = A[m][:] @ W[:,n] + bias ----------------
// Block tile 128m x 128n, k-tile 32. 8 warps: warp_m = wid&3 (32m), warp_n = wid>>2 (64n).
#define ASTR 36
#define BSTR 136
__global__ __launch_bounds__(256, 2) void gemm_mma()
{
    __shared__ float sAh[128 * ASTR];
    __shared__ float sAl[128 * ASTR];
    __shared__ float sBh[32 * BSTR];
    __shared__ float sBl[32 * BSTR];

    const int bn = blockIdx.x, bm = blockIdx.y;
    const int tid = threadIdx.x;
    const int wid = tid >> 5, lane = tid & 31;
    const int wm = wid & 3, wn = wid >> 2;
    const int g = lane >> 2, tg = lane & 3;

    float acc[2][8][4];
#pragma unroll
    for (int mt = 0; mt < 2; mt++)
#pragma unroll
        for (int nt = 0; nt < 8; nt++)
#pragma unroll
            for (int i = 0; i < 4; i++) acc[mt][nt][i] = 0.f;

    for (int k0 = 0; k0 < VD; k0 += 32) {
        __syncthreads();
        // stage A tile: 128 rows x 32 k (hi+lo)
#pragma unroll
        for (int i = 0; i < 4; i++) {
            int idx = tid + i * 256;              // 0..1023
            int row = idx >> 3, kq = (idx & 7) * 4;
            size_t ga = (size_t)(bm * 128 + row) * VD + k0 + kq;
            float4 vh = *(const float4*)(g_Ahi + ga);
            float4 vl = *(const float4*)(g_Alo + ga);
            *(float4*)(sAh + row * ASTR + kq) = vh;
            *(float4*)(sAl + row * ASTR + kq) = vl;
        }
        // stage B tile: 32 k x 128 n (hi+lo)
#pragma unroll
        for (int i = 0; i < 4; i++) {
            int idx = tid + i * 256;
            int row = idx >> 5, nq = (idx & 31) * 4;
            size_t gb = (size_t)(k0 + row) * NT + bn * 128 + nq;
            float4 vh = *(const float4*)(g_Whi + gb);
            float4 vl = *(const float4*)(g_Wlo + gb);
            *(float4*)(sBh + row * BSTR + nq) = vh;
            *(float4*)(sBl + row * BSTR + nq) = vl;
        }
        __syncthreads();

#pragma unroll
        for (int ks = 0; ks < 4; ks++) {
            const int kb = ks * 8;
            uint32_t ah[2][4], al[2][4];
#pragma unroll
            for (int mt = 0; mt < 2; mt++) {
                int m0 = wm * 32 + mt * 16;
                ah[mt][0] = __float_as_uint(sAh[(m0 + g) * ASTR + kb + tg]);
                ah[mt][1] = __float_as_uint(sAh[(m0 + g + 8) * ASTR + kb + tg]);
                ah[mt][2] = __float_as_uint(sAh[(m0 + g) * ASTR + kb + tg + 4]);
                ah[mt][3] = __float_as_uint(sAh[(m0 + g + 8) * ASTR + kb + tg + 4]);
                al[mt][0] = __float_as_uint(sAl[(m0 + g) * ASTR + kb + tg]);
                al[mt][1] = __float_as_uint(sAl[(m0 + g + 8) * ASTR + kb + tg]);
                al[mt][2] = __float_as_uint(sAl[(m0 + g) * ASTR + kb + tg + 4]);
                al[mt][3] = __float_as_uint(sAl[(m0 + g + 8) * ASTR + kb + tg + 4]);
            }
#pragma unroll
            for (int nt = 0; nt < 8; nt++) {
                int n0 = wn * 64 + nt * 8;
                uint32_t bh[2], bl[2];
                bh[0] = __float_as_uint(sBh[(kb + tg) * BSTR + n0 + g]);
                bh[1] = __float_as_uint(sBh[(kb + tg + 4) * BSTR + n0 + g]);
                bl[0] = __float_as_uint(sBl[(kb + tg) * BSTR + n0 + g]);
                bl[1] = __float_as_uint(sBl[(kb + tg + 4) * BSTR + n0 + g]);
#pragma unroll
                for (int mt = 0; mt < 2; mt++) {
                    mma8(acc[mt][nt], ah[mt], bh);
                    mma8(acc[mt][nt], ah[mt], bl);
                    mma8(acc[mt][nt], al[mt], bh);
                }
            }
        }
    }

    // epilogue: route to the right [t][n][b] buffer. All 128 block cols in one region.
    float* outp;
    int noff, Nl;
    if (bn < 16)      { outp = g_xgf;  noff = 0;    Nl = 2048; }
    else if (bn < 32) { outp = g_xgb;  noff = 2048; Nl = 2048; }
    else              { outp = g_skip; noff = 4096; Nl = 1024; }

#pragma unroll
    for (int mt = 0; mt < 2; mt++) {
        int m0 = bm * 128 + wm * 32 + mt * 16 + g;
#pragma unroll
        for (int nt = 0; nt < 8; nt++) {
            int ng = bn * 128 + wn * 64 + nt * 8 + 2 * tg;   // global col of acc[.][0]
            float bias0 = g_biasc[ng], bias1 = g_biasc[ng + 1];
            int nl = ng - noff;
#pragma unroll
            for (int half = 0; half < 2; half++) {
                int m = m0 + half * 8;
                int tt = m >> 5, bb = m & 31;
                size_t base = (size_t)tt * Nl * Bz + (size_t)nl * Bz + bb;
                outp[base]      = acc[mt][nt][half * 2 + 0] + bias0;
                outp[base + Bz] = acc[mt][nt][half * 2 + 1] + bias1;
            }
        }
    }
}

// ---------------- persistent bidirectional LSTM recurrence ----------------
__device__ __forceinline__ float sigm(float x) { return 1.f / (1.f + expf(-x)); }

__device__ __forceinline__ unsigned ld_acq(const unsigned* p) {
    unsigned v;
    asm volatile("ld.acquire.gpu.u32 %0, [%1];" : "=r"(v) : "l"(p) : "memory");
    return v;
}
__device__ __forceinline__ void st_rel(unsigned* p, unsigned v) {
    asm volatile("st.release.gpu.u32 [%0], %1;" :: "l"(p), "r"(v) : "memory");
}

__device__ __forceinline__ void grid_bar() {
    __syncthreads();
    if (threadIdx.x == 0) {
        __threadfence();
        unsigned g = ld_acq(&gbar_gen);
        unsigned old = atomicAdd(&gbar_cnt, 1u);
        if (old == NBLK - 1) {
            gbar_cnt = 0;
            st_rel(&gbar_gen, g + 1);
        } else {
            while (ld_acq(&gbar_gen) == g) { __nanosleep(64); }
        }
    }
    __syncthreads();
}

__global__ __launch_bounds__(256, 1) void lstm_recur(
    const float* __restrict__ Whf,
    const float* __restrict__ Whb,
    const float* __restrict__ alphas)
{
    extern __shared__ float smem[];
    float4* w4 = (float4*)smem;          // [c(8)][k(512)]  64 KB
    float* sh_h = smem + 16384;          // [k(512)][b(32)] 64 KB

    const int bid = blockIdx.x;
    const int dir = (bid >= NBLK / 2) ? 1 : 0;
    const int blk = dir ? bid - NBLK / 2 : bid;
    const float* Wh = dir ? Whb : Whf;
    const float* xg = dir ? g_xgb : g_xgf;
    float* hs = dir ? g_hsb : g_hsf;

    const int tid = threadIdx.x;
    const int c = tid >> 5;
    const int lane = tid & 31;
    const int j = blk * 8 + c;

    for (int k = lane; k < HD; k += 32) {
        const float* wr = Wh + (size_t)k * 2048 + j;
        w4[c * 512 + k] = make_float4(wr[0], wr[512], wr[1024], wr[1536]);
    }
    __syncthreads();

    float cst = 0.f, hprev = 0.f;
    const float4* wp = w4 + c * 512;

    for (int s = 0; s < SL; s++) {
        const int t = dir ? (SL - 1 - s) : s;

        // ---- prefetch step inputs FIRST (independent of h) ----
        const size_t base = (size_t)t * (2048 * Bz) + lane;
        float xi = xg[base + (size_t)(0 * HD + j) * Bz];
        float xf = xg[base + (size_t)(1 * HD + j) * Bz];
        float xv = xg[base + (size_t)(2 * HD + j) * Bz];
        float xo = xg[base + (size_t)(3 * HD + j) * Bz];
        float a  = alphas[lane * SL + t];

        if (s > 0) {  // stage h(s-1) from global double-buffer
            const float4* src = (const float4*)(g_h + (size_t)(dir * 2 + ((s + 1) & 1)) * (HD * Bz));
            float4* dst = (float4*)sh_h;
#pragma unroll 4
            for (int i = tid; i < (HD * Bz) / 4; i += 256) dst[i] = __ldcg(src + i);
        }
        __syncthreads();

        float ai = 0.f, af = 0.f, ag = 0.f, ao = 0.f;
        if (s > 0) {
            const float* hp = sh_h + lane;
#pragma unroll 8
            for (int k = 0; k < HD; k++) {
                float4 w = wp[k];
                float hv = hp[k * 32];
                ai = fmaf(w.x, hv, ai);
                af = fmaf(w.y, hv, af);
                ag = fmaf(w.z, hv, ag);
                ao = fmaf(w.w, hv, ao);
            }
        }

        float gi = sigm(ai + xi);
        float gf = sigm(af + xf);
        float gg = tanhf(ag + xv);
        float go = sigm(ao + xo);

        float cn = gf * cst + gi * gg;
        float hn = go * tanhf(cn);

        cst = a * cn + (1.f - a) * cst;
        float h2 = a * hn + (1.f - a) * hprev;
        hprev = h2;

        hs[(size_t)t * (HD * Bz) + j * 32 + lane] = h2;
        g_h[(size_t)(dir * 2 + (s & 1)) * (HD * Bz) + j * 32 + lane] = h2;

        grid_bar();
    }
}

// ---------------- pooling ----------------
__global__ void pool_kernel(const float* __restrict__ alphas, float* __restrict__ out)
{
    const int tid = blockIdx.x * blockDim.x + threadIdx.x;
    const int b = tid & 31;
    const int g = tid >> 5;
    if (g >= 1024) return;

    const float* top = (g < HD) ? (g_hsf + (size_t)g * 32 + b)
                                : (g_hsb + (size_t)(g - HD) * 32 + b);
    const float* sk = g_skip + (size_t)g * 32 + b;

    float sum = 0.f, asum = 0.f, mx = -INFINITY;
    for (int t = 0; t < SL; t++) {
        float a = alphas[b * SL + t];
        float r = (top[(size_t)t * (HD * Bz)] + sk[(size_t)t * (1024 * Bz)]) * a;
        sum += r;
        asum += a;
        if (a > 0.f) mx = fmaxf(mx, r);
    }
    float mean = sum / (asum + 1e-6f);
    if (isinf(mx)) mx = 0.f;
    out[b * 2048 + g] = mean;
    out[b * 2048 + 1024 + g] = mx;
}

// ---------------- launch ----------------
extern "C" void kernel_launch(void* const* d_in, const int* in_sizes, int n_in,
                              void* d_out, int out_size)
{
    const float* values = (const float*)d_in[0];
    const float* alphas = (const float*)d_in[1];
    const float* Wx_f = (const float*)d_in[2];
    const float* Wh_f = (const float*)d_in[3];
    const float* b_f  = (const float*)d_in[4];
    const float* Wx_b = (const float*)d_in[5];
    const float* Wh_b = (const float*)d_in[6];
    const float* b_b  = (const float*)d_in[7];
    const float* Ws   = (const float*)d_in[8];
    const float* bs   = (const float*)d_in[9];
    float* out = (float*)d_out;

    cudaFuncSetAttribute(lstm_recur, cudaFuncAttributeMaxDynamicSharedMemorySize, 131072);

    split_A<<<Bz * SL, 256>>>(values);
    split_W<<<VD, 256>>>(Wx_f, Wx_b, Ws, b_f, b_b, bs);
    gemm_mma<<<dim3(NT / 128, (Bz * SL) / 128), 256>>>();
    lstm_recur<<<NBLK, 256, 131072>>>(Wh_f, Wh_b, alphas);
    pool_kernel<<<(Bz * 1024) / 256, 256>>>(alphas, out);
}

// round 5
// speedup vs baseline: 1.7657x; 1.0246x over previous
#include <cuda_runtime.h>
#include <math.h>
#include <stdint.h>

#define Bz 32
#define SL 512
#define VD 768
#define HD 512
#define NT 5120     // fused N: 2048 (Wx_f) + 2048 (Wx_b) + 1024 (Ws)
#define NBLK 128    // 64 fwd + 64 bwd persistent blocks

// ---------------- scratch (device globals; no allocation allowed) ----------------
__device__ __align__(16) float g_xgf[(size_t)SL * 2048 * Bz];   // [t][g][b]
__device__ __align__(16) float g_xgb[(size_t)SL * 2048 * Bz];   // [t][g][b]
__device__ __align__(16) float g_skip[(size_t)SL * 1024 * Bz];  // [t][g][b]
__device__ __align__(16) float g_hsf[(size_t)SL * HD * Bz];     // [t][j][b]
__device__ __align__(16) float g_hsb[(size_t)SL * HD * Bz];     // [t][j][b]
__device__ __align__(16) float g_hbc[2 * 2 * HD * Bz];          // [dir][parity][k][b]
__device__ int g_flag[NBLK];                                    // per-block step counters

// tf32-split operands for the input-projection GEMM
__device__ __align__(16) float g_Ahi[(size_t)(Bz * SL) * VD];
__device__ __align__(16) float g_Alo[(size_t)(Bz * SL) * VD];
__device__ __align__(16) float g_Whi[(size_t)VD * NT];
__device__ __align__(16) float g_Wlo[(size_t)VD * NT];
__device__ __align__(16) float g_biasc[NT];

// ---------------- helpers ----------------
__device__ __forceinline__ float to_tf32(float x) {
    float r;
    asm("cvt.rna.tf32.f32 %0, %1;" : "=f"(r) : "f"(x));
    return r;
}
__device__ __forceinline__ void mma8(float* d, const uint32_t* a, const uint32_t* b) {
    asm volatile(
        "mma.sync.aligned.m16n8k8.row.col.f32.tf32.tf32.f32 "
        "{%0,%1,%2,%3}, {%4,%5,%6,%7}, {%8,%9}, {%0,%1,%2,%3};"
        : "+f"(d[0]), "+f"(d[1]), "+f"(d[2]), "+f"(d[3])
        : "r"(a[0]), "r"(a[1]), "r"(a[2]), "r"(a[3]), "r"(b[0]), "r"(b[1]));
}
__device__ __forceinline__ int ld_acq_i(const int* p) {
    int v;
    asm volatile("ld.acquire.gpu.s32 %0, [%1];" : "=r"(v) : "l"(p) : "memory");
    return v;
}
__device__ __forceinline__ void st_rel_i(int* p, int v) {
    asm volatile("st.release.gpu.s32 [%0], %1;" :: "l"(p), "r"(v) : "memory");
}
__device__ __forceinline__ float sigm_f(float x) {
    return __fdividef(1.f, 1.f + __expf(-x));
}
__device__ __forceinline__ float tanh_f(float x) {
    return __fdividef(2.f, 1.f + __expf(-2.f * x)) - 1.f;
}

// ---------------- init (graph-replay safe reset) ----------------
__global__ void init_flags() {
    if (threadIdx.x < NBLK) g_flag[threadIdx.x] = 0;
}

// ---------------- split kernels ----------------
__global__ void split_A(const float* __restrict__ values) {
    const int m = blockIdx.x;              // m = t*32 + b
    const int b = m & 31, t = m >> 5;
    const float* src = values + ((size_t)b * SL + t) * VD;
    for (int v = threadIdx.x; v < VD; v += 256) {
        float x = src[v];
        float hi = to_tf32(x);
        g_Ahi[(size_t)m * VD + v] = hi;
        g_Alo[(size_t)m * VD + v] = to_tf32(x - hi);
    }
}

__global__ void split_W(const float* __restrict__ Wxf, const float* __restrict__ Wxb,
                        const float* __restrict__ Ws,
                        const float* __restrict__ bf, const float* __restrict__ bb_,
                        const float* __restrict__ bs) {
    const int r = blockIdx.x;  // 0..767
    for (int c = threadIdx.x; c < NT; c += 256) {
        float x = (c < 2048) ? Wxf[(size_t)r * 2048 + c]
                : (c < 4096) ? Wxb[(size_t)r * 2048 + (c - 2048)]
                             : Ws[(size_t)r * 1024 + (c - 4096)];
        float hi = to_tf32(x);
        g_Whi[(size_t)r * NT + c] = hi;
        g_Wlo[(size_t)r * NT + c] = to_tf32(x - hi);
    }
    if (r == 0) {
        for (int c = threadIdx.x; c < NT; c += 256)
            g_biasc[c] = (c < 2048) ? bf[c] : (c < 4096) ? bb_[c - 2048] : bs[c - 4096];
    }
}

// ---------------- fused tf32 3x GEMM (input projections) ----------------
#define ASTR 36
#define BSTR 136
__global__ __launch_bounds__(256, 2) void gemm_mma()
{
    __shared__ float sAh[128 * ASTR];
    __shared__ float sAl[128 * ASTR];
    __shared__ float sBh[32 * BSTR];
    __shared__ float sBl[32 * BSTR];

    const int bn = blockIdx.x, bm = blockIdx.y;
    const int tid = threadIdx.x;
    const int wid = tid >> 5, lane = tid & 31;
    const int wm = wid & 3, wn = wid >> 2;
    const int g = lane >> 2, tg = lane & 3;

    float acc[2][8][4];
#pragma unroll
    for (int mt = 0; mt < 2; mt++)
#pragma unroll
        for (int nt = 0; nt < 8; nt++)
#pragma unroll
            for (int i = 0; i < 4; i++) acc[mt][nt][i] = 0.f;

    for (int k0 = 0; k0 < VD; k0 += 32) {
        __syncthreads();
#pragma unroll
        for (int i = 0; i < 4; i++) {
            int idx = tid + i * 256;
            int row = idx >> 3, kq = (idx & 7) * 4;
            size_t ga = (size_t)(bm * 128 + row) * VD + k0 + kq;
            *(float4*)(sAh + row * ASTR + kq) = *(const float4*)(g_Ahi + ga);
            *(float4*)(sAl + row * ASTR + kq) = *(const float4*)(g_Alo + ga);
        }
#pragma unroll
        for (int i = 0; i < 4; i++) {
            int idx = tid + i * 256;
            int row = idx >> 5, nq = (idx & 31) * 4;
            size_t gb = (size_t)(k0 + row) * NT + bn * 128 + nq;
            *(float4*)(sBh + row * BSTR + nq) = *(const float4*)(g_Whi + gb);
            *(float4*)(sBl + row * BSTR + nq) = *(const float4*)(g_Wlo + gb);
        }
        __syncthreads();

#pragma unroll
        for (int ks = 0; ks < 4; ks++) {
            const int kb = ks * 8;
            uint32_t ah[2][4], al[2][4];
#pragma unroll
            for (int mt = 0; mt < 2; mt++) {
                int m0 = wm * 32 + mt * 16;
                ah[mt][0] = __float_as_uint(sAh[(m0 + g) * ASTR + kb + tg]);
                ah[mt][1] = __float_as_uint(sAh[(m0 + g + 8) * ASTR + kb + tg]);
                ah[mt][2] = __float_as_uint(sAh[(m0 + g) * ASTR + kb + tg + 4]);
                ah[mt][3] = __float_as_uint(sAh[(m0 + g + 8) * ASTR + kb + tg + 4]);
                al[mt][0] = __float_as_uint(sAl[(m0 + g) * ASTR + kb + tg]);
                al[mt][1] = __float_as_uint(sAl[(m0 + g + 8) * ASTR + kb + tg]);
                al[mt][2] = __float_as_uint(sAl[(m0 + g) * ASTR + kb + tg + 4]);
                al[mt][3] = __float_as_uint(sAl[(m0 + g + 8) * ASTR + kb + tg + 4]);
            }
#pragma unroll
            for (int nt = 0; nt < 8; nt++) {
                int n0 = wn * 64 + nt * 8;
                uint32_t bh[2], bl[2];
                bh[0] = __float_as_uint(sBh[(kb + tg) * BSTR + n0 + g]);
                bh[1] = __float_as_uint(sBh[(kb + tg + 4) * BSTR + n0 + g]);
                bl[0] = __float_as_uint(sBl[(kb + tg) * BSTR + n0 + g]);
                bl[1] = __float_as_uint(sBl[(kb + tg + 4) * BSTR + n0 + g]);
#pragma unroll
                for (int mt = 0; mt < 2; mt++) {
                    mma8(acc[mt][nt], ah[mt], bh);
                    mma8(acc[mt][nt], ah[mt], bl);
                    mma8(acc[mt][nt], al[mt], bh);
                }
            }
        }
    }

    float* outp;
    int noff, Nl;
    if (bn < 16)      { outp = g_xgf;  noff = 0;    Nl = 2048; }
    else if (bn < 32) { outp = g_xgb;  noff = 2048; Nl = 2048; }
    else              { outp = g_skip; noff = 4096; Nl = 1024; }

#pragma unroll
    for (int mt = 0; mt < 2; mt++) {
        int m0 = bm * 128 + wm * 32 + mt * 16 + g;
#pragma unroll
        for (int nt = 0; nt < 8; nt++) {
            int ng = bn * 128 + wn * 64 + nt * 8 + 2 * tg;
            float bias0 = g_biasc[ng], bias1 = g_biasc[ng + 1];
            int nl = ng - noff;
#pragma unroll
            for (int half = 0; half < 2; half++) {
                int m = m0 + half * 8;
                int tt = m >> 5, bb = m & 31;
                size_t base = (size_t)tt * Nl * Bz + (size_t)nl * Bz + bb;
                outp[base]      = acc[mt][nt][half * 2 + 0] + bias0;
                outp[base + Bz] = acc[mt][nt][half * 2 + 1] + bias1;
            }
        }
    }
}

// ---------------- persistent tensor-core bidirectional LSTM recurrence ----------------
// 128 blocks (64/dir). Block owns 8 h-columns j = blk*8..blk*8+7.
// Block N=32 cols, gate-interleaved: n = 4*j_local + gate. M=32 (batch), K=512.
// Warp w (0..7): k-tiles kt = 8w..8w+7, ALL 4 n-tiles, both m-tiles.
// Wh fragments (hi+lo) resident in registers: [4 nt][8 ktl][2 regs] x2 = 128 regs.
// smem: sAhi/sAlo (A-frag layout [ (mt*64+kt)*4+reg ][lane], 64 KB each) + gs partials.
#define SM_AHI 0
#define SM_ALO 16384
#define SM_GS  32768            // gs[8][32][36] floats
#define SM_TOTAL_F (32768 + 8 * 32 * 36)

__global__ __launch_bounds__(256, 1) void lstm_mma(
    const float* __restrict__ Whf,
    const float* __restrict__ Whb,
    const float* __restrict__ alphas)
{
    extern __shared__ float smem[];
    float* sAhi = smem + SM_AHI;
    float* sAlo = smem + SM_ALO;
    float* gs   = smem + SM_GS;

    const int bid = blockIdx.x;
    const int dir = (bid >= 64) ? 1 : 0;
    const int blk = dir ? bid - 64 : bid;
    const float* Wh = dir ? Whb : Whf;
    const float* xg = dir ? g_xgb : g_xgf;
    float* hs = dir ? g_hsb : g_hsf;
    float* hbc = g_hbc + (size_t)dir * 2 * HD * Bz;
    int* flags = g_flag + dir * 64;

    const int tid = threadIdx.x;
    const int wid = tid >> 5, lane = tid & 31;
    const int g = lane >> 2, tg = lane & 3;
    // cell role: thread owns (j_local, batch)
    const int cb = tid & 31;
    const int cjl = tid >> 5;
    const int cj = blk * 8 + cjl;

    // ---- preload Wh fragments into registers (hi + lo) ----
    float whi[4][8][2], wlo[4][8][2];
#pragma unroll
    for (int nt = 0; nt < 4; nt++) {
        int n = nt * 8 + g;                 // block col
        int gate = n & 3, jl = n >> 2;
        int col = gate * 512 + blk * 8 + jl;
#pragma unroll
        for (int kl = 0; kl < 8; kl++) {
            int kt = wid * 8 + kl;
#pragma unroll
            for (int r = 0; r < 2; r++) {
                int k = kt * 8 + tg + (r ? 4 : 0);
                float v = Wh[(size_t)k * 2048 + col];
                float hi = to_tf32(v);
                whi[nt][kl][r] = hi;
                wlo[nt][kl][r] = to_tf32(v - hi);
            }
        }
    }

    float cst = 0.f, hprev = 0.f;

    for (int s = 0; s < SL; s++) {
        const int t = dir ? (SL - 1 - s) : s;

        // ---- prefetch xg gates + alpha (independent of h) ----
        const size_t xb = (size_t)t * (2048 * Bz) + cb;
        float xi = xg[xb + (size_t)(0 * 512 + cj) * Bz];
        float xf = xg[xb + (size_t)(1 * 512 + cj) * Bz];
        float xv = xg[xb + (size_t)(2 * 512 + cj) * Bz];
        float xo = xg[xb + (size_t)(3 * 512 + cj) * Bz];
        float a  = alphas[cb * SL + t];

        float pi = 0.f, pf = 0.f, pg = 0.f, po = 0.f;

        if (s > 0) {
            // ---- wait for h(s-1) from all 64 producers of this direction ----
            if (wid == 0) {
                for (;;) {
                    int v1 = ld_acq_i(&flags[lane]);
                    int v2 = ld_acq_i(&flags[lane + 32]);
                    if (__all_sync(0xffffffffu, (v1 >= s) && (v2 >= s))) break;
                    __nanosleep(20);
                }
            }
            __syncthreads();

            // ---- stage h(s-1): global [k][b] -> smem A-frag layout, fused hi/lo split ----
            {
                const float4* src = (const float4*)(hbc + (size_t)((s - 1) & 1) * (HD * Bz));
#pragma unroll 4
                for (int i = tid; i < (HD * Bz) / 4; i += 256) {
                    float4 v = __ldcg(src + i);
                    int e = i * 4;
                    int k = e >> 5, b0 = e & 31;
                    int mt = b0 >> 4;
                    int kt = k >> 3, c = k & 7;
                    int tg2 = c & 3;
                    int rbase = (c >= 4) ? 2 : 0;
                    int slot = (mt * 64 + kt) * 4;
                    float hv[4] = {v.x, v.y, v.z, v.w};
#pragma unroll
                    for (int q = 0; q < 4; q++) {
                        int b = b0 + q;
                        int reg = rbase + (((b & 15) >= 8) ? 1 : 0);
                        int ln = (b & 7) * 4 + tg2;
                        int idx = (slot + reg) * 32 + ln;
                        float hi = to_tf32(hv[q]);
                        sAhi[idx] = hi;
                        sAlo[idx] = to_tf32(hv[q] - hi);
                    }
                }
            }
            __syncthreads();

            // ---- mma: 3-chain tf32, W in registers ----
            float acc[2][4][4];
#pragma unroll
            for (int mt = 0; mt < 2; mt++)
#pragma unroll
                for (int nt = 0; nt < 4; nt++)
#pragma unroll
                    for (int i = 0; i < 4; i++) acc[mt][nt][i] = 0.f;

#pragma unroll
            for (int kl = 0; kl < 8; kl++) {
                int kt = wid * 8 + kl;
                uint32_t ah[2][4], al[2][4];
#pragma unroll
                for (int mt = 0; mt < 2; mt++) {
                    int slot = (mt * 64 + kt) * 4;
#pragma unroll
                    for (int r = 0; r < 4; r++) {
                        ah[mt][r] = __float_as_uint(sAhi[(slot + r) * 32 + lane]);
                        al[mt][r] = __float_as_uint(sAlo[(slot + r) * 32 + lane]);
                    }
                }
#pragma unroll
                for (int nt = 0; nt < 4; nt++) {
                    uint32_t bh[2] = { __float_as_uint(whi[nt][kl][0]),
                                       __float_as_uint(whi[nt][kl][1]) };
                    uint32_t bl[2] = { __float_as_uint(wlo[nt][kl][0]),
                                       __float_as_uint(wlo[nt][kl][1]) };
#pragma unroll
                    for (int mt = 0; mt < 2; mt++) {
                        mma8(acc[mt][nt], ah[mt], bh);
                        mma8(acc[mt][nt], ah[mt], bl);
                        mma8(acc[mt][nt], al[mt], bh);
                    }
                }
            }

            // ---- write partial gate sums: gs[wid][b][n] ----
#pragma unroll
            for (int mt = 0; mt < 2; mt++) {
#pragma unroll
                for (int nt = 0; nt < 4; nt++) {
                    int row0 = mt * 16 + g;
                    int col = nt * 8 + 2 * tg;
                    int b0i = (wid * 32 + row0) * 36 + col;
                    gs[b0i]     = acc[mt][nt][0];
                    gs[b0i + 1] = acc[mt][nt][1];
                    int b1i = (wid * 32 + row0 + 8) * 36 + col;
                    gs[b1i]     = acc[mt][nt][2];
                    gs[b1i + 1] = acc[mt][nt][3];
                }
            }
            __syncthreads();

            // ---- reduce 8 k-partials for this thread's (jl, b) ----
#pragma unroll
            for (int w = 0; w < 8; w++) {
                int base = (w * 32 + cb) * 36 + cjl * 4;
                pi += gs[base + 0];
                pf += gs[base + 1];
                pg += gs[base + 2];
                po += gs[base + 3];
            }
        }

        // ---- LSTM cell ----
        float gi = sigm_f(pi + xi);
        float gf = sigm_f(pf + xf);
        float gG = tanh_f(pg + xv);
        float go = sigm_f(po + xo);

        float cn = gf * cst + gi * gG;
        float hn = go * tanh_f(cn);

        cst = a * cn + (1.f - a) * cst;
        float h2 = a * hn + (1.f - a) * hprev;
        hprev = h2;

        hs[(size_t)t * (HD * Bz) + cj * 32 + cb] = h2;
        hbc[(size_t)(s & 1) * (HD * Bz) + cj * 32 + cb] = h2;

        // ---- publish completion ----
        __threadfence();
        __syncthreads();
        if (tid == 0) st_rel_i(&flags[blk], s + 1);
    }
}

// ---------------- pooling ----------------
__global__ void pool_kernel(const float* __restrict__ alphas, float* __restrict__ out)
{
    const int tid = blockIdx.x * blockDim.x + threadIdx.x;
    const int b = tid & 31;
    const int g = tid >> 5;
    if (g >= 1024) return;

    const float* top = (g < HD) ? (g_hsf + (size_t)g * 32 + b)
                                : (g_hsb + (size_t)(g - HD) * 32 + b);
    const float* sk = g_skip + (size_t)g * 32 + b;

    float sum = 0.f, asum = 0.f, mx = -INFINITY;
    for (int t = 0; t < SL; t++) {
        float a = alphas[b * SL + t];
        float r = (top[(size_t)t * (HD * Bz)] + sk[(size_t)t * (1024 * Bz)]) * a;
        sum += r;
        asum += a;
        if (a > 0.f) mx = fmaxf(mx, r);
    }
    float mean = sum / (asum + 1e-6f);
    if (isinf(mx)) mx = 0.f;
    out[b * 2048 + g] = mean;
    out[b * 2048 + 1024 + g] = mx;
}

// ---------------- launch ----------------
extern "C" void kernel_launch(void* const* d_in, const int* in_sizes, int n_in,
                              void* d_out, int out_size)
{
    const float* values = (const float*)d_in[0];
    const float* alphas = (const float*)d_in[1];
    const float* Wx_f = (const float*)d_in[2];
    const float* Wh_f = (const float*)d_in[3];
    const float* b_f  = (const float*)d_in[4];
    const float* Wx_b = (const float*)d_in[5];
    const float* Wh_b = (const float*)d_in[6];
    const float* b_b  = (const float*)d_in[7];
    const float* Ws   = (const float*)d_in[8];
    const float* bs   = (const float*)d_in[9];
    float* out = (float*)d_out;

    cudaFuncSetAttribute(lstm_mma, cudaFuncAttributeMaxDynamicSharedMemorySize,
                         SM_TOTAL_F * sizeof(float));

    init_flags<<<1, NBLK>>>();
    split_A<<<Bz * SL, 256>>>(values);
    split_W<<<VD, 256>>>(Wx_f, Wx_b, Ws, b_f, b_b, bs);
    gemm_mma<<<dim3(NT / 128, (Bz * SL) / 128), 256>>>();
    lstm_mma<<<NBLK, 256, SM_TOTAL_F * sizeof(float)>>>(Wh_f, Wh_b, alphas);
    pool_kernel<<<(Bz * 1024) / 256, 256>>>(alphas, out);
}

// round 7
// speedup vs baseline: 3.2207x; 1.8240x over previous
// R7 = R6 resubmit (R6 bench hit "container failed twice" — infra-flake signature,
// same as R2->R3 which passed unchanged). Audited sync protocol / residency /
// frag mappings; no hang path found.
#include <cuda_runtime.h>
#include <cuda_bf16.h>
#include <math.h>
#include <stdint.h>

#define Bz 32
#define SL 512
#define VD 768
#define HD 512
#define NT 5120     // fused N: 2048 (Wx_f) + 2048 (Wx_b) + 1024 (Ws)
#define NBLK 128    // 64 fwd + 64 bwd persistent blocks

// ---------------- scratch (device globals; no allocation allowed) ----------------
__device__ __align__(16) float g_xgf[(size_t)SL * 2048 * Bz];   // [t][g][b]
__device__ __align__(16) float g_xgb[(size_t)SL * 2048 * Bz];   // [t][g][b]
__device__ __align__(16) float g_skip[(size_t)SL * 1024 * Bz];  // [t][g][b]
__device__ __align__(16) float g_hsf[(size_t)SL * HD * Bz];     // [t][j][b]
__device__ __align__(16) float g_hsb[(size_t)SL * HD * Bz];     // [t][j][b]
// h broadcast in A-fragment layout, bf16 hi/lo planes: [dir][parity][8192 u32]
__device__ __align__(16) uint32_t g_hbh[2 * 2 * 8192];
__device__ __align__(16) uint32_t g_hbl[2 * 2 * 8192];
__device__ int g_flag[NBLK];

// bf16-split GEMM operands
__device__ __align__(16) __nv_bfloat16 g_Ah[(size_t)(Bz * SL) * VD];  // [m][k]
__device__ __align__(16) __nv_bfloat16 g_Al[(size_t)(Bz * SL) * VD];
__device__ __align__(16) __nv_bfloat16 g_Wth[(size_t)NT * VD];        // W^T [n][k]
__device__ __align__(16) __nv_bfloat16 g_Wtl[(size_t)NT * VD];
__device__ __align__(16) float g_biasc[NT];

// ---------------- helpers ----------------
__device__ __forceinline__ void bsplit(float x, __nv_bfloat16& hi, __nv_bfloat16& lo) {
    hi = __float2bfloat16_rn(x);
    lo = __float2bfloat16_rn(x - __bfloat162float(hi));
}
__device__ __forceinline__ uint32_t bpack(__nv_bfloat16 a, __nv_bfloat16 b) {
    uint16_t ua = *(uint16_t*)&a, ub = *(uint16_t*)&b;
    return (uint32_t)ua | ((uint32_t)ub << 16);
}
__device__ __forceinline__ void mma16(float* d, const uint32_t* a, const uint32_t* b) {
    asm volatile(
        "mma.sync.aligned.m16n8k16.row.col.f32.bf16.bf16.f32 "
        "{%0,%1,%2,%3}, {%4,%5,%6,%7}, {%8,%9}, {%0,%1,%2,%3};"
        : "+f"(d[0]), "+f"(d[1]), "+f"(d[2]), "+f"(d[3])
        : "r"(a[0]), "r"(a[1]), "r"(a[2]), "r"(a[3]), "r"(b[0]), "r"(b[1]));
}
__device__ __forceinline__ int ld_acq_i(const int* p) {
    int v;
    asm volatile("ld.acquire.gpu.s32 %0, [%1];" : "=r"(v) : "l"(p) : "memory");
    return v;
}
__device__ __forceinline__ void st_rel_i(int* p, int v) {
    asm volatile("st.release.gpu.s32 [%0], %1;" :: "l"(p), "r"(v) : "memory");
}
__device__ __forceinline__ float sigm_f(float x) { return __fdividef(1.f, 1.f + __expf(-x)); }
__device__ __forceinline__ float tanh_f(float x) { return __fdividef(2.f, 1.f + __expf(-2.f * x)) - 1.f; }

// ---------------- init: flags + bias concat ----------------
__global__ void init_misc(const float* __restrict__ bf, const float* __restrict__ bb_,
                          const float* __restrict__ bs) {
    int c = blockIdx.x * 256 + threadIdx.x;
    if (c < NT)
        g_biasc[c] = (c < 2048) ? bf[c] : (c < 4096) ? bb_[c - 2048] : bs[c - 4096];
    if (blockIdx.x == 0 && threadIdx.x < NBLK) g_flag[threadIdx.x] = 0;
}

// ---------------- split A (values -> bf16 hi/lo planes, [m][k]) ----------------
__global__ void split_A(const float* __restrict__ values) {
    const int m = blockIdx.x;              // m = t*32 + b
    const int b = m & 31, t = m >> 5;
    const float* src = values + ((size_t)b * SL + t) * VD;
    for (int v = threadIdx.x; v < VD; v += 256) {
        __nv_bfloat16 hi, lo;
        bsplit(src[v], hi, lo);
        g_Ah[(size_t)m * VD + v] = hi;
        g_Al[(size_t)m * VD + v] = lo;
    }
}

// ---------------- split + transpose W -> [n][k] bf16 hi/lo ----------------
__global__ void split_W(const float* __restrict__ Wxf, const float* __restrict__ Wxb,
                        const float* __restrict__ Ws) {
    __shared__ float tile[32][33];
    const int k0 = blockIdx.x * 32;   // 24 blocks
    const int n0 = blockIdx.y * 32;   // 160 blocks
    const int tid = threadIdx.x;
    const int c = tid & 31;           // n-local on load
    for (int r = tid >> 5; r < 32; r += 8) {
        int k = k0 + r, n = n0 + c;
        float x = (n < 2048) ? Wxf[(size_t)k * 2048 + n]
                : (n < 4096) ? Wxb[(size_t)k * 2048 + (n - 2048)]
                             : Ws[(size_t)k * 1024 + (n - 4096)];
        tile[r][c] = x;
    }
    __syncthreads();
    for (int r = tid >> 5; r < 32; r += 8) {
        int n = n0 + r, k = k0 + c;
        __nv_bfloat16 hi, lo;
        bsplit(tile[c][r], hi, lo);
        g_Wth[(size_t)n * VD + k] = hi;
        g_Wtl[(size_t)n * VD + k] = lo;
    }
}

// ---------------- fused bf16 3-chain GEMM (input projections) ----------------
// C[m][n] = A[m][:] @ W[:,n] + bias. Block 128m x 128n, k-tile 32.
#define GSTR 56
__global__ __launch_bounds__(256, 2) void gemm_mma()
{
    extern __shared__ uint16_t gsm[];
    uint16_t* sAh = gsm;                 // 128*56
    uint16_t* sAl = gsm + 7168;
    uint16_t* sBh = gsm + 14336;
    uint16_t* sBl = gsm + 21504;

    const int bn = blockIdx.x, bm = blockIdx.y;
    const int tid = threadIdx.x;
    const int wid = tid >> 5, lane = tid & 31;
    const int wm = wid & 3, wn = wid >> 2;
    const int g = lane >> 2, tg = lane & 3;

    float acc[2][8][4];
#pragma unroll
    for (int mt = 0; mt < 2; mt++)
#pragma unroll
        for (int nt = 0; nt < 8; nt++)
#pragma unroll
            for (int i = 0; i < 4; i++) acc[mt][nt][i] = 0.f;

    const int srow = tid >> 2, sq = (tid & 3) * 8;

    for (int k0 = 0; k0 < VD; k0 += 32) {
        __syncthreads();
#pragma unroll
        for (int half = 0; half < 2; half++) {
            int row = srow + half * 64;
            size_t ga = (size_t)(bm * 128 + row) * VD + k0 + sq;
            size_t gb = (size_t)(bn * 128 + row) * VD + k0 + sq;
            *(float4*)(sAh + row * GSTR + sq) = *(const float4*)(g_Ah + ga);
            *(float4*)(sAl + row * GSTR + sq) = *(const float4*)(g_Al + ga);
            *(float4*)(sBh + row * GSTR + sq) = *(const float4*)(g_Wth + gb);
            *(float4*)(sBl + row * GSTR + sq) = *(const float4*)(g_Wtl + gb);
        }
        __syncthreads();

#pragma unroll
        for (int kc = 0; kc < 2; kc++) {
            const int kb = kc * 16 + 2 * tg;
            uint32_t ah[2][4], al[2][4];
#pragma unroll
            for (int mt = 0; mt < 2; mt++) {
                int m0 = wm * 32 + mt * 16;
                ah[mt][0] = *(const uint32_t*)(sAh + (m0 + g) * GSTR + kb);
                ah[mt][1] = *(const uint32_t*)(sAh + (m0 + g + 8) * GSTR + kb);
                ah[mt][2] = *(const uint32_t*)(sAh + (m0 + g) * GSTR + kb + 8);
                ah[mt][3] = *(const uint32_t*)(sAh + (m0 + g + 8) * GSTR + kb + 8);
                al[mt][0] = *(const uint32_t*)(sAl + (m0 + g) * GSTR + kb);
                al[mt][1] = *(const uint32_t*)(sAl + (m0 + g + 8) * GSTR + kb);
                al[mt][2] = *(const uint32_t*)(sAl + (m0 + g) * GSTR + kb + 8);
                al[mt][3] = *(const uint32_t*)(sAl + (m0 + g + 8) * GSTR + kb + 8);
            }
#pragma unroll
            for (int nt = 0; nt < 8; nt++) {
                int n0 = wn * 64 + nt * 8;
                uint32_t bh[2], bl[2];
                bh[0] = *(const uint32_t*)(sBh + (n0 + g) * GSTR + kb);
                bh[1] = *(const uint32_t*)(sBh + (n0 + g) * GSTR + kb + 8);
                bl[0] = *(const uint32_t*)(sBl + (n0 + g) * GSTR + kb);
                bl[1] = *(const uint32_t*)(sBl + (n0 + g) * GSTR + kb + 8);
#pragma unroll
                for (int mt = 0; mt < 2; mt++) {
                    mma16(acc[mt][nt], ah[mt], bh);
                    mma16(acc[mt][nt], ah[mt], bl);
                    mma16(acc[mt][nt], al[mt], bh);
                }
            }
        }
    }

    float* outp;
    int noff, Nl;
    if (bn < 16)      { outp = g_xgf;  noff = 0;    Nl = 2048; }
    else if (bn < 32) { outp = g_xgb;  noff = 2048; Nl = 2048; }
    else              { outp = g_skip; noff = 4096; Nl = 1024; }

#pragma unroll
    for (int mt = 0; mt < 2; mt++) {
        int m0 = bm * 128 + wm * 32 + mt * 16 + g;
#pragma unroll
        for (int nt = 0; nt < 8; nt++) {
            int ng = bn * 128 + wn * 64 + nt * 8 + 2 * tg;
            float bias0 = g_biasc[ng], bias1 = g_biasc[ng + 1];
            int nl = ng - noff;
#pragma unroll
            for (int half = 0; half < 2; half++) {
                int m = m0 + half * 8;
                int tt = m >> 5, bb = m & 31;
                size_t base = (size_t)tt * Nl * Bz + (size_t)nl * Bz + bb;
                outp[base]      = acc[mt][nt][half * 2 + 0] + bias0;
                outp[base + Bz] = acc[mt][nt][half * 2 + 1] + bias1;
            }
        }
    }
}

// ---------------- persistent bf16 tensor-core bidirectional LSTM ----------------
#define SM_AH 0
#define SM_AL 8192
#define SM_GS 16384          // u32 offset; gs = 8*32*36 floats
#define SM_LSTM_BYTES ((16384 + 8 * 32 * 36) * 4)

__global__ __launch_bounds__(256, 1) void lstm_mma(
    const float* __restrict__ Whf,
    const float* __restrict__ Whb,
    const float* __restrict__ alphas)
{
    extern __shared__ uint32_t smem32[];
    uint32_t* sAh = smem32 + SM_AH;
    uint32_t* sAl = smem32 + SM_AL;
    float* gs = (float*)(smem32 + SM_GS);

    const int bid = blockIdx.x;
    const int dir = (bid >= 64) ? 1 : 0;
    const int blk = dir ? bid - 64 : bid;
    const float* Wh = dir ? Whb : Whf;
    const float* xg = dir ? g_xgb : g_xgf;
    float* hs = dir ? g_hsb : g_hsf;
    int* flags = g_flag + dir * 64;

    const int tid = threadIdx.x;
    const int wid = tid >> 5, lane = tid & 31;
    const int g = lane >> 2, tg = lane & 3;
    const int cb = tid & 31;
    const int cjl = tid >> 5;
    const int cj = blk * 8 + cjl;

    const int kk = cj & 15, kt_own = cj >> 4;
    const int ro = cb & 15, mt_own = cb >> 4;
    const int reg_own = ((ro >= 8) ? 1 : 0) + ((kk >= 8) ? 2 : 0);
    const int ln_own = (ro & 7) * 4 + ((kk >> 1) & 3);
    const int widx = ((mt_own * 32 + kt_own) * 32 + ln_own) * 4 + reg_own;
    const int half_own = kk & 1;

    float whi[4][4][2], wlo[4][4][2];
#pragma unroll
    for (int nt = 0; nt < 4; nt++) {
        int n = nt * 8 + g;
        int gate = n & 3, jl = n >> 2;
        int col = gate * 512 + blk * 8 + jl;
#pragma unroll
        for (int ktl = 0; ktl < 4; ktl++) {
            int kt = wid * 4 + ktl;
#pragma unroll
            for (int r = 0; r < 2; r++) {
                int k = kt * 16 + r * 8 + 2 * tg;
                float w0 = Wh[(size_t)k * 2048 + col];
                float w1 = Wh[(size_t)(k + 1) * 2048 + col];
                __nv_bfloat16 h0, l0, h1, l1;
                bsplit(w0, h0, l0);
                bsplit(w1, h1, l1);
                whi[nt][ktl][r] = __uint_as_float(bpack(h0, h1));
                wlo[nt][ktl][r] = __uint_as_float(bpack(l0, l1));
            }
        }
    }

    float cst = 0.f, hprev = 0.f;

    for (int s = 0; s < SL; s++) {
        const int t = dir ? (SL - 1 - s) : s;

        const size_t xb = (size_t)t * (2048 * Bz) + cb;
        float xi = xg[xb + (size_t)(0 * 512 + cj) * Bz];
        float xf = xg[xb + (size_t)(1 * 512 + cj) * Bz];
        float xv = xg[xb + (size_t)(2 * 512 + cj) * Bz];
        float xo = xg[xb + (size_t)(3 * 512 + cj) * Bz];
        float a  = alphas[cb * SL + t];

        float pi = 0.f, pf = 0.f, pg = 0.f, po = 0.f;

        if (s > 0) {
            if (wid == 0) {
                for (;;) {
                    int v1 = ld_acq_i(&flags[lane]);
                    int v2 = ld_acq_i(&flags[lane + 32]);
                    if (__all_sync(0xffffffffu, (v1 >= s) && (v2 >= s))) break;
                    __nanosleep(20);
                }
            }
            __syncthreads();

            {
                const int par = (s - 1) & 1;
                const float4* srch = (const float4*)(g_hbh + (size_t)(dir * 2 + par) * 8192);
                const float4* srcl = (const float4*)(g_hbl + (size_t)(dir * 2 + par) * 8192);
                float4* dsth = (float4*)sAh;
                float4* dstl = (float4*)sAl;
#pragma unroll
                for (int i = 0; i < 8; i++) {
                    int idx = tid + i * 256;
                    dsth[idx] = __ldcg(srch + idx);
                    dstl[idx] = __ldcg(srcl + idx);
                }
            }
            __syncthreads();

            float acc[2][4][4];
#pragma unroll
            for (int mt = 0; mt < 2; mt++)
#pragma unroll
                for (int nt = 0; nt < 4; nt++)
#pragma unroll
                    for (int i = 0; i < 4; i++) acc[mt][nt][i] = 0.f;

#pragma unroll
            for (int ktl = 0; ktl < 4; ktl++) {
                int kt = wid * 4 + ktl;
                uint32_t ah[2][4], al[2][4];
#pragma unroll
                for (int mt = 0; mt < 2; mt++) {
                    uint4 vh = *(const uint4*)(sAh + ((mt * 32 + kt) * 32 + lane) * 4);
                    uint4 vl = *(const uint4*)(sAl + ((mt * 32 + kt) * 32 + lane) * 4);
                    ah[mt][0] = vh.x; ah[mt][1] = vh.y; ah[mt][2] = vh.z; ah[mt][3] = vh.w;
                    al[mt][0] = vl.x; al[mt][1] = vl.y; al[mt][2] = vl.z; al[mt][3] = vl.w;
                }
#pragma unroll
                for (int nt = 0; nt < 4; nt++) {
                    uint32_t bh[2] = { __float_as_uint(whi[nt][ktl][0]),
                                       __float_as_uint(whi[nt][ktl][1]) };
                    uint32_t bl[2] = { __float_as_uint(wlo[nt][ktl][0]),
                                       __float_as_uint(wlo[nt][ktl][1]) };
#pragma unroll
                    for (int mt = 0; mt < 2; mt++) {
                        mma16(acc[mt][nt], ah[mt], bh);
                        mma16(acc[mt][nt], ah[mt], bl);
                        mma16(acc[mt][nt], al[mt], bh);
                    }
                }
            }

#pragma unroll
            for (int mt = 0; mt < 2; mt++) {
#pragma unroll
                for (int nt = 0; nt < 4; nt++) {
                    int row0 = mt * 16 + g;
                    int col = nt * 8 + 2 * tg;
                    int b0i = (wid * 32 + row0) * 36 + col;
                    gs[b0i]     = acc[mt][nt][0];
                    gs[b0i + 1] = acc[mt][nt][1];
                    int b1i = (wid * 32 + row0 + 8) * 36 + col;
                    gs[b1i]     = acc[mt][nt][2];
                    gs[b1i + 1] = acc[mt][nt][3];
                }
            }
            __syncthreads();

#pragma unroll
            for (int w = 0; w < 8; w++) {
                int base = (w * 32 + cb) * 36 + cjl * 4;
                pi += gs[base + 0];
                pf += gs[base + 1];
                pg += gs[base + 2];
                po += gs[base + 3];
            }
        }

        float gi = sigm_f(pi + xi);
        float gf = sigm_f(pf + xf);
        float gG = tanh_f(pg + xv);
        float go = sigm_f(po + xo);

        float cn = gf * cst + gi * gG;
        float hn = go * tanh_f(cn);

        cst = a * cn + (1.f - a) * cst;
        float h2 = a * hn + (1.f - a) * hprev;
        hprev = h2;

        hs[(size_t)t * (HD * Bz) + cj * 32 + cb] = h2;

        {
            __nv_bfloat16 hi, lo;
            bsplit(h2, hi, lo);
            size_t pbase = (size_t)(dir * 2 + (s & 1)) * 8192;
            ((__nv_bfloat16*)(g_hbh + pbase))[widx * 2 + half_own] = hi;
            ((__nv_bfloat16*)(g_hbl + pbase))[widx * 2 + half_own] = lo;
        }

        __threadfence();
        __syncthreads();
        if (tid == 0) st_rel_i(&flags[blk], s + 1);
    }
}

// ---------------- pooling ----------------
__global__ void pool_kernel(const float* __restrict__ alphas, float* __restrict__ out)
{
    const int tid = blockIdx.x * blockDim.x + threadIdx.x;
    const int b = tid & 31;
    const int g = tid >> 5;
    if (g >= 1024) return;

    const float* top = (g < HD) ? (g_hsf + (size_t)g * 32 + b)
                                : (g_hsb + (size_t)(g - HD) * 32 + b);
    const float* sk = g_skip + (size_t)g * 32 + b;

    float sum = 0.f, asum = 0.f, mx = -INFINITY;
    for (int t = 0; t < SL; t++) {
        float a = alphas[b * SL + t];
        float r = (top[(size_t)t * (HD * Bz)] + sk[(size_t)t * (1024 * Bz)]) * a;
        sum += r;
        asum += a;
        if (a > 0.f) mx = fmaxf(mx, r);
    }
    float mean = sum / (asum + 1e-6f);
    if (isinf(mx)) mx = 0.f;
    out[b * 2048 + g] = mean;
    out[b * 2048 + 1024 + g] = mx;
}

// ---------------- launch ----------------
extern "C" void kernel_launch(void* const* d_in, const int* in_sizes, int n_in,
                              void* d_out, int out_size)
{
    const float* values = (const float*)d_in[0];
    const float* alphas = (const float*)d_in[1];
    const float* Wx_f = (const float*)d_in[2];
    const float* Wh_f = (const float*)d_in[3];
    const float* b_f  = (const float*)d_in[4];
    const float* Wx_b = (const float*)d_in[5];
    const float* Wh_b = (const float*)d_in[6];
    const float* b_b  = (const float*)d_in[7];
    const float* Ws   = (const float*)d_in[8];
    const float* bs   = (const float*)d_in[9];
    float* out = (float*)d_out;

    cudaFuncSetAttribute(gemm_mma, cudaFuncAttributeMaxDynamicSharedMemorySize, 57344);
    cudaFuncSetAttribute(lstm_mma, cudaFuncAttributeMaxDynamicSharedMemorySize, SM_LSTM_BYTES);

    init_misc<<<20, 256>>>(b_f, b_b, bs);
    split_A<<<Bz * SL, 256>>>(values);
    split_W<<<dim3(VD / 32, NT / 32), 256>>>(Wx_f, Wx_b, Ws);
    gemm_mma<<<dim3(NT / 128, (Bz * SL) / 128), 256, 57344>>>();
    lstm_mma<<<NBLK, 256, SM_LSTM_BYTES>>>(Wh_f, Wh_b, alphas);
    pool_kernel<<<(Bz * 1024) / 256, 256>>>(alphas, out);
}

// round 9
// speedup vs baseline: 3.6143x; 1.1222x over previous
// R8: recurrence reads A-fragments directly from L2 via LDG.128 (broadcast buffer is
// already in frag layout) — removes 64KB/step smem staging + 2 barriers per block.
// GEMM unchanged from R7 (isolating the recurrence change).
#include <cuda_runtime.h>
#include <cuda_bf16.h>
#include <math.h>
#include <stdint.h>

#define Bz 32
#define SL 512
#define VD 768
#define HD 512
#define NT 5120     // fused N: 2048 (Wx_f) + 2048 (Wx_b) + 1024 (Ws)
#define NBLK 128    // 64 fwd + 64 bwd persistent blocks

// ---------------- scratch (device globals; no allocation allowed) ----------------
__device__ __align__(16) float g_xgf[(size_t)SL * 2048 * Bz];   // [t][g][b]
__device__ __align__(16) float g_xgb[(size_t)SL * 2048 * Bz];   // [t][g][b]
__device__ __align__(16) float g_skip[(size_t)SL * 1024 * Bz];  // [t][g][b]
__device__ __align__(16) float g_hsf[(size_t)SL * HD * Bz];     // [t][j][b]
__device__ __align__(16) float g_hsb[(size_t)SL * HD * Bz];     // [t][j][b]
// h broadcast in A-fragment layout, bf16 hi/lo planes: [dir][parity][8192 u32]
__device__ __align__(16) uint32_t g_hbh[2 * 2 * 8192];
__device__ __align__(16) uint32_t g_hbl[2 * 2 * 8192];
__device__ int g_flag[NBLK];

// bf16-split GEMM operands
__device__ __align__(16) __nv_bfloat16 g_Ah[(size_t)(Bz * SL) * VD];  // [m][k]
__device__ __align__(16) __nv_bfloat16 g_Al[(size_t)(Bz * SL) * VD];
__device__ __align__(16) __nv_bfloat16 g_Wth[(size_t)NT * VD];        // W^T [n][k]
__device__ __align__(16) __nv_bfloat16 g_Wtl[(size_t)NT * VD];
__device__ __align__(16) float g_biasc[NT];

// ---------------- helpers ----------------
__device__ __forceinline__ void bsplit(float x, __nv_bfloat16& hi, __nv_bfloat16& lo) {
    hi = __float2bfloat16_rn(x);
    lo = __float2bfloat16_rn(x - __bfloat162float(hi));
}
__device__ __forceinline__ uint32_t bpack(__nv_bfloat16 a, __nv_bfloat16 b) {
    uint16_t ua = *(uint16_t*)&a, ub = *(uint16_t*)&b;
    return (uint32_t)ua | ((uint32_t)ub << 16);
}
__device__ __forceinline__ void mma16(float* d, const uint32_t* a, const uint32_t* b) {
    asm volatile(
        "mma.sync.aligned.m16n8k16.row.col.f32.bf16.bf16.f32 "
        "{%0,%1,%2,%3}, {%4,%5,%6,%7}, {%8,%9}, {%0,%1,%2,%3};"
        : "+f"(d[0]), "+f"(d[1]), "+f"(d[2]), "+f"(d[3])
        : "r"(a[0]), "r"(a[1]), "r"(a[2]), "r"(a[3]), "r"(b[0]), "r"(b[1]));
}
__device__ __forceinline__ int ld_acq_i(const int* p) {
    int v;
    asm volatile("ld.acquire.gpu.s32 %0, [%1];" : "=r"(v) : "l"(p) : "memory");
    return v;
}
__device__ __forceinline__ void st_rel_i(int* p, int v) {
    asm volatile("st.release.gpu.s32 [%0], %1;" :: "l"(p), "r"(v) : "memory");
}
__device__ __forceinline__ float sigm_f(float x) { return __fdividef(1.f, 1.f + __expf(-x)); }
__device__ __forceinline__ float tanh_f(float x) { return __fdividef(2.f, 1.f + __expf(-2.f * x)) - 1.f; }

// ---------------- init: flags + bias concat ----------------
__global__ void init_misc(const float* __restrict__ bf, const float* __restrict__ bb_,
                          const float* __restrict__ bs) {
    int c = blockIdx.x * 256 + threadIdx.x;
    if (c < NT)
        g_biasc[c] = (c < 2048) ? bf[c] : (c < 4096) ? bb_[c - 2048] : bs[c - 4096];
    if (blockIdx.x == 0 && threadIdx.x < NBLK) g_flag[threadIdx.x] = 0;
}

// ---------------- split A (values -> bf16 hi/lo planes, [m][k]) ----------------
__global__ void split_A(const float* __restrict__ values) {
    const int m = blockIdx.x;              // m = t*32 + b
    const int b = m & 31, t = m >> 5;
    const float* src = values + ((size_t)b * SL + t) * VD;
    for (int v = threadIdx.x; v < VD; v += 256) {
        __nv_bfloat16 hi, lo;
        bsplit(src[v], hi, lo);
        g_Ah[(size_t)m * VD + v] = hi;
        g_Al[(size_t)m * VD + v] = lo;
    }
}

// ---------------- split + transpose W -> [n][k] bf16 hi/lo ----------------
__global__ void split_W(const float* __restrict__ Wxf, const float* __restrict__ Wxb,
                        const float* __restrict__ Ws) {
    __shared__ float tile[32][33];
    const int k0 = blockIdx.x * 32;
    const int n0 = blockIdx.y * 32;
    const int tid = threadIdx.x;
    const int c = tid & 31;
    for (int r = tid >> 5; r < 32; r += 8) {
        int k = k0 + r, n = n0 + c;
        float x = (n < 2048) ? Wxf[(size_t)k * 2048 + n]
                : (n < 4096) ? Wxb[(size_t)k * 2048 + (n - 2048)]
                             : Ws[(size_t)k * 1024 + (n - 4096)];
        tile[r][c] = x;
    }
    __syncthreads();
    for (int r = tid >> 5; r < 32; r += 8) {
        int n = n0 + r, k = k0 + c;
        __nv_bfloat16 hi, lo;
        bsplit(tile[c][r], hi, lo);
        g_Wth[(size_t)n * VD + k] = hi;
        g_Wtl[(size_t)n * VD + k] = lo;
    }
}

// ---------------- fused bf16 3-chain GEMM (input projections) ----------------
#define GSTR 56
__global__ __launch_bounds__(256, 2) void gemm_mma()
{
    extern __shared__ uint16_t gsm[];
    uint16_t* sAh = gsm;
    uint16_t* sAl = gsm + 7168;
    uint16_t* sBh = gsm + 14336;
    uint16_t* sBl = gsm + 21504;

    const int bn = blockIdx.x, bm = blockIdx.y;
    const int tid = threadIdx.x;
    const int wid = tid >> 5, lane = tid & 31;
    const int wm = wid & 3, wn = wid >> 2;
    const int g = lane >> 2, tg = lane & 3;

    float acc[2][8][4];
#pragma unroll
    for (int mt = 0; mt < 2; mt++)
#pragma unroll
        for (int nt = 0; nt < 8; nt++)
#pragma unroll
            for (int i = 0; i < 4; i++) acc[mt][nt][i] = 0.f;

    const int srow = tid >> 2, sq = (tid & 3) * 8;

    for (int k0 = 0; k0 < VD; k0 += 32) {
        __syncthreads();
#pragma unroll
        for (int half = 0; half < 2; half++) {
            int row = srow + half * 64;
            size_t ga = (size_t)(bm * 128 + row) * VD + k0 + sq;
            size_t gb = (size_t)(bn * 128 + row) * VD + k0 + sq;
            *(float4*)(sAh + row * GSTR + sq) = *(const float4*)(g_Ah + ga);
            *(float4*)(sAl + row * GSTR + sq) = *(const float4*)(g_Al + ga);
            *(float4*)(sBh + row * GSTR + sq) = *(const float4*)(g_Wth + gb);
            *(float4*)(sBl + row * GSTR + sq) = *(const float4*)(g_Wtl + gb);
        }
        __syncthreads();

#pragma unroll
        for (int kc = 0; kc < 2; kc++) {
            const int kb = kc * 16 + 2 * tg;
            uint32_t ah[2][4], al[2][4];
#pragma unroll
            for (int mt = 0; mt < 2; mt++) {
                int m0 = wm * 32 + mt * 16;
                ah[mt][0] = *(const uint32_t*)(sAh + (m0 + g) * GSTR + kb);
                ah[mt][1] = *(const uint32_t*)(sAh + (m0 + g + 8) * GSTR + kb);
                ah[mt][2] = *(const uint32_t*)(sAh + (m0 + g) * GSTR + kb + 8);
                ah[mt][3] = *(const uint32_t*)(sAh + (m0 + g + 8) * GSTR + kb + 8);
                al[mt][0] = *(const uint32_t*)(sAl + (m0 + g) * GSTR + kb);
                al[mt][1] = *(const uint32_t*)(sAl + (m0 + g + 8) * GSTR + kb);
                al[mt][2] = *(const uint32_t*)(sAl + (m0 + g) * GSTR + kb + 8);
                al[mt][3] = *(const uint32_t*)(sAl + (m0 + g + 8) * GSTR + kb + 8);
            }
#pragma unroll
            for (int nt = 0; nt < 8; nt++) {
                int n0 = wn * 64 + nt * 8;
                uint32_t bh[2], bl[2];
                bh[0] = *(const uint32_t*)(sBh + (n0 + g) * GSTR + kb);
                bh[1] = *(const uint32_t*)(sBh + (n0 + g) * GSTR + kb + 8);
                bl[0] = *(const uint32_t*)(sBl + (n0 + g) * GSTR + kb);
                bl[1] = *(const uint32_t*)(sBl + (n0 + g) * GSTR + kb + 8);
#pragma unroll
                for (int mt = 0; mt < 2; mt++) {
                    mma16(acc[mt][nt], ah[mt], bh);
                    mma16(acc[mt][nt], ah[mt], bl);
                    mma16(acc[mt][nt], al[mt], bh);
                }
            }
        }
    }

    float* outp;
    int noff, Nl;
    if (bn < 16)      { outp = g_xgf;  noff = 0;    Nl = 2048; }
    else if (bn < 32) { outp = g_xgb;  noff = 2048; Nl = 2048; }
    else              { outp = g_skip; noff = 4096; Nl = 1024; }

#pragma unroll
    for (int mt = 0; mt < 2; mt++) {
        int m0 = bm * 128 + wm * 32 + mt * 16 + g;
#pragma unroll
        for (int nt = 0; nt < 8; nt++) {
            int ng = bn * 128 + wn * 64 + nt * 8 + 2 * tg;
            float bias0 = g_biasc[ng], bias1 = g_biasc[ng + 1];
            int nl = ng - noff;
#pragma unroll
            for (int half = 0; half < 2; half++) {
                int m = m0 + half * 8;
                int tt = m >> 5, bb = m & 31;
                size_t base = (size_t)tt * Nl * Bz + (size_t)nl * Bz + bb;
                outp[base]      = acc[mt][nt][half * 2 + 0] + bias0;
                outp[base + Bz] = acc[mt][nt][half * 2 + 1] + bias1;
            }
        }
    }
}

// ---------------- persistent bf16 tensor-core bidirectional LSTM ----------------
// Direct-LDG A-fragments; smem holds only the gs partial-sum buffer.
#define SM_LSTM_BYTES (8 * 32 * 36 * 4)

__global__ __launch_bounds__(256, 1) void lstm_mma(
    const float* __restrict__ Whf,
    const float* __restrict__ Whb,
    const float* __restrict__ alphas)
{
    extern __shared__ float gs[];   // [8][32][36]

    const int bid = blockIdx.x;
    const int dir = (bid >= 64) ? 1 : 0;
    const int blk = dir ? bid - 64 : bid;
    const float* Wh = dir ? Whb : Whf;
    const float* xg = dir ? g_xgb : g_xgf;
    float* hs = dir ? g_hsb : g_hsf;
    int* flags = g_flag + dir * 64;

    const int tid = threadIdx.x;
    const int wid = tid >> 5, lane = tid & 31;
    const int g = lane >> 2, tg = lane & 3;
    const int cb = tid & 31;
    const int cjl = tid >> 5;
    const int cj = blk * 8 + cjl;

    // fixed fragment-slot of this thread's h element (k=cj, row=cb)
    const int kk = cj & 15, kt_own = cj >> 4;
    const int ro = cb & 15, mt_own = cb >> 4;
    const int reg_own = ((ro >= 8) ? 1 : 0) + ((kk >= 8) ? 2 : 0);
    const int ln_own = (ro & 7) * 4 + ((kk >> 1) & 3);
    const int widx = ((mt_own * 32 + kt_own) * 32 + ln_own) * 4 + reg_own;
    const int half_own = kk & 1;

    // ---- preload Wh fragments (hi/lo, packed bf16x2 along k) ----
    float whi[4][4][2], wlo[4][4][2];
#pragma unroll
    for (int nt = 0; nt < 4; nt++) {
        int n = nt * 8 + g;
        int gate = n & 3, jl = n >> 2;
        int col = gate * 512 + blk * 8 + jl;
#pragma unroll
        for (int ktl = 0; ktl < 4; ktl++) {
            int kt = wid * 4 + ktl;
#pragma unroll
            for (int r = 0; r < 2; r++) {
                int k = kt * 16 + r * 8 + 2 * tg;
                float w0 = Wh[(size_t)k * 2048 + col];
                float w1 = Wh[(size_t)(k + 1) * 2048 + col];
                __nv_bfloat16 h0, l0, h1, l1;
                bsplit(w0, h0, l0);
                bsplit(w1, h1, l1);
                whi[nt][ktl][r] = __uint_as_float(bpack(h0, h1));
                wlo[nt][ktl][r] = __uint_as_float(bpack(l0, l1));
            }
        }
    }

    float cst = 0.f, hprev = 0.f;

    for (int s = 0; s < SL; s++) {
        const int t = dir ? (SL - 1 - s) : s;

        // prefetch xg gates + alpha (independent of h)
        const size_t xb = (size_t)t * (2048 * Bz) + cb;
        float xi = xg[xb + (size_t)(0 * 512 + cj) * Bz];
        float xf = xg[xb + (size_t)(1 * 512 + cj) * Bz];
        float xv = xg[xb + (size_t)(2 * 512 + cj) * Bz];
        float xo = xg[xb + (size_t)(3 * 512 + cj) * Bz];
        float a  = alphas[cb * SL + t];

        float pi = 0.f, pf = 0.f, pg = 0.f, po = 0.f;

        if (s > 0) {
            // wait for all 64 producers of this direction
            if (wid == 0) {
                for (;;) {
                    int v1 = ld_acq_i(&flags[lane]);
                    int v2 = ld_acq_i(&flags[lane + 32]);
                    if (__all_sync(0xffffffffu, (v1 >= s) && (v2 >= s))) break;
                    __nanosleep(20);
                }
            }
            __syncthreads();

            // ---- load A-fragments straight from L2 (frag-layout broadcast buffer) ----
            const size_t pbase = (size_t)(dir * 2 + ((s - 1) & 1)) * 8192;
            const uint4* fhp = (const uint4*)(g_hbh + pbase);
            const uint4* flp = (const uint4*)(g_hbl + pbase);
            uint4 fh[2][4], fl[2][4];
#pragma unroll
            for (int mt = 0; mt < 2; mt++)
#pragma unroll
                for (int ktl = 0; ktl < 4; ktl++) {
                    int kt = wid * 4 + ktl;
                    fh[mt][ktl] = __ldcg(fhp + (mt * 32 + kt) * 32 + lane);
                    fl[mt][ktl] = __ldcg(flp + (mt * 32 + kt) * 32 + lane);
                }

            float acc[2][4][4];
#pragma unroll
            for (int mt = 0; mt < 2; mt++)
#pragma unroll
                for (int nt = 0; nt < 4; nt++)
#pragma unroll
                    for (int i = 0; i < 4; i++) acc[mt][nt][i] = 0.f;

#pragma unroll
            for (int ktl = 0; ktl < 4; ktl++) {
                uint32_t ah[2][4], al[2][4];
#pragma unroll
                for (int mt = 0; mt < 2; mt++) {
                    ah[mt][0] = fh[mt][ktl].x; ah[mt][1] = fh[mt][ktl].y;
                    ah[mt][2] = fh[mt][ktl].z; ah[mt][3] = fh[mt][ktl].w;
                    al[mt][0] = fl[mt][ktl].x; al[mt][1] = fl[mt][ktl].y;
                    al[mt][2] = fl[mt][ktl].z; al[mt][3] = fl[mt][ktl].w;
                }
#pragma unroll
                for (int nt = 0; nt < 4; nt++) {
                    uint32_t bh[2] = { __float_as_uint(whi[nt][ktl][0]),
                                       __float_as_uint(whi[nt][ktl][1]) };
                    uint32_t bl[2] = { __float_as_uint(wlo[nt][ktl][0]),
                                       __float_as_uint(wlo[nt][ktl][1]) };
#pragma unroll
                    for (int mt = 0; mt < 2; mt++) {
                        mma16(acc[mt][nt], ah[mt], bh);
                        mma16(acc[mt][nt], ah[mt], bl);
                        mma16(acc[mt][nt], al[mt], bh);
                    }
                }
            }

            // write partial gate sums: gs[wid][b][n]
#pragma unroll
            for (int mt = 0; mt < 2; mt++) {
#pragma unroll
                for (int nt = 0; nt < 4; nt++) {
                    int row0 = mt * 16 + g;
                    int col = nt * 8 + 2 * tg;
                    int b0i = (wid * 32 + row0) * 36 + col;
                    gs[b0i]     = acc[mt][nt][0];
                    gs[b0i + 1] = acc[mt][nt][1];
                    int b1i = (wid * 32 + row0 + 8) * 36 + col;
                    gs[b1i]     = acc[mt][nt][2];
                    gs[b1i + 1] = acc[mt][nt][3];
                }
            }
            __syncthreads();

#pragma unroll
            for (int w = 0; w < 8; w++) {
                int base = (w * 32 + cb) * 36 + cjl * 4;
                pi += gs[base + 0];
                pf += gs[base + 1];
                pg += gs[base + 2];
                po += gs[base + 3];
            }
        }

        // LSTM cell
        float gi = sigm_f(pi + xi);
        float gf = sigm_f(pf + xf);
        float gG = tanh_f(pg + xv);
        float go = sigm_f(po + xo);

        float cn = gf * cst + gi * gG;
        float hn = go * tanh_f(cn);

        cst = a * cn + (1.f - a) * cst;
        float h2 = a * hn + (1.f - a) * hprev;
        hprev = h2;

        hs[(size_t)t * (HD * Bz) + cj * 32 + cb] = h2;

        // publish h in frag layout, pre-split bf16 hi/lo
        {
            __nv_bfloat16 hi, lo;
            bsplit(h2, hi, lo);
            size_t pbase = (size_t)(dir * 2 + (s & 1)) * 8192;
            ((__nv_bfloat16*)(g_hbh + pbase))[widx * 2 + half_own] = hi;
            ((__nv_bfloat16*)(g_hbl + pbase))[widx * 2 + half_own] = lo;
        }

        __threadfence();
        __syncthreads();
        if (tid == 0) st_rel_i(&flags[blk], s + 1);
    }
}

// ---------------- pooling ----------------
__global__ void pool_kernel(const float* __restrict__ alphas, float* __restrict__ out)
{
    const int tid = blockIdx.x * blockDim.x + threadIdx.x;
    const int b = tid & 31;
    const int g = tid >> 5;
    if (g >= 1024) return;

    const float* top = (g < HD) ? (g_hsf + (size_t)g * 32 + b)
                                : (g_hsb + (size_t)(g - HD) * 32 + b);
    const float* sk = g_skip + (size_t)g * 32 + b;

    float sum = 0.f, asum = 0.f, mx = -INFINITY;
    for (int t = 0; t < SL; t++) {
        float a = alphas[b * SL + t];
        float r = (top[(size_t)t * (HD * Bz)] + sk[(size_t)t * (1024 * Bz)]) * a;
        sum += r;
        asum += a;
        if (a > 0.f) mx = fmaxf(mx, r);
    }
    float mean = sum / (asum + 1e-6f);
    if (isinf(mx)) mx = 0.f;
    out[b * 2048 + g] = mean;
    out[b * 2048 + 1024 + g] = mx;
}

// ---------------- launch ----------------
extern "C" void kernel_launch(void* const* d_in, const int* in_sizes, int n_in,
                              void* d_out, int out_size)
{
    const float* values = (const float*)d_in[0];
    const float* alphas = (const float*)d_in[1];
    const float* Wx_f = (const float*)d_in[2];
    const float* Wh_f = (const float*)d_in[3];
    const float* b_f  = (const float*)d_in[4];
    const float* Wx_b = (const float*)d_in[5];
    const float* Wh_b = (const float*)d_in[6];
    const float* b_b  = (const float*)d_in[7];
    const float* Ws   = (const float*)d_in[8];
    const float* bs   = (const float*)d_in[9];
    float* out = (float*)d_out;

    cudaFuncSetAttribute(gemm_mma, cudaFuncAttributeMaxDynamicSharedMemorySize, 57344);
    cudaFuncSetAttribute(lstm_mma, cudaFuncAttributeMaxDynamicSharedMemorySize, SM_LSTM_BYTES);

    init_misc<<<20, 256>>>(b_f, b_b, bs);
    split_A<<<Bz * SL, 256>>>(values);
    split_W<<<dim3(VD / 32, NT / 32), 256>>>(Wx_f, Wx_b, Ws);
    gemm_mma<<<dim3(NT / 128, (Bz * SL) / 128), 256, 57344>>>();
    lstm_mma<<<NBLK, 256, SM_LSTM_BYTES>>>(Wh_f, Wh_b, alphas);
    pool_kernel<<<(Bz * 1024) / 256, 256>>>(alphas, out);
}